// round 1
// baseline (speedup 1.0000x reference)
#include <cuda_runtime.h>
#include <cuda_bf16.h>

// ShiftImgPreprocessor: out[b,t,c,i,j] = img[b,t,c, clamp(i+sy-PAD,0,H-1),
//                                              clamp(j+sx-PAD,0,W-1)] / 255 - 0.5
// shapes: img (256,4,3,96,96) fp32, shift (256,2) int32 (sx=shift[b][0], sy=shift[b][1])
// Pure HBM-streaming gather. One thread per output float4 (W=96 -> 24 float4/row).

#define PAD 4
#define N_IMG 256
#define T_IMG 4
#define C_IMG 3
#define H_IMG 96
#define W_IMG 96
#define W4 (W_IMG / 4)
#define TC (T_IMG * C_IMG)
#define TOTAL4 (N_IMG * T_IMG * C_IMG * H_IMG * W4)

__global__ __launch_bounds__(256) void shift_img_kernel(
    const float* __restrict__ img,
    const int*   __restrict__ shift,
    float*       __restrict__ out)
{
    int tid = blockIdx.x * blockDim.x + threadIdx.x;
    if (tid >= TOTAL4) return;

    const float INV255 = 1.0f / 255.0f;

    int j4      = tid % W4;          // which float4 within the row
    int row     = tid / W4;          // global row index: (b*T*C + t*C + c)*H + i
    int i       = row % H_IMG;
    int img_idx = row / H_IMG;       // flattened (b,t,c)
    int b       = img_idx / TC;

    int sx = __ldg(&shift[2 * b + 0]);
    int sy = __ldg(&shift[2 * b + 1]);

    int srcY = i + sy - PAD;
    srcY = min(max(srcY, 0), H_IMG - 1);

    const float* src = img + (size_t)img_idx * (H_IMG * W_IMG) + (size_t)srcY * W_IMG;

    int j = j4 * 4;
    int xoff = j + sx - PAD;

    float4 v;
    int x0 = min(max(xoff + 0, 0), W_IMG - 1);
    int x1 = min(max(xoff + 1, 0), W_IMG - 1);
    int x2 = min(max(xoff + 2, 0), W_IMG - 1);
    int x3 = min(max(xoff + 3, 0), W_IMG - 1);

    v.x = fmaf(__ldg(src + x0), INV255, -0.5f);
    v.y = fmaf(__ldg(src + x1), INV255, -0.5f);
    v.z = fmaf(__ldg(src + x2), INV255, -0.5f);
    v.w = fmaf(__ldg(src + x3), INV255, -0.5f);

    reinterpret_cast<float4*>(out)[tid] = v;
}

extern "C" void kernel_launch(void* const* d_in, const int* in_sizes, int n_in,
                              void* d_out, int out_size)
{
    const float* img   = (const float*)d_in[0];
    const int*   shift = (const int*)d_in[1];
    float*       out   = (float*)d_out;

    int blocks = (TOTAL4 + 255) / 256;
    shift_img_kernel<<<blocks, 256>>>(img, shift, out);
}

// round 2
// speedup vs baseline: 1.0104x; 1.0104x over previous
#include <cuda_runtime.h>
#include <cuda_bf16.h>

// ShiftImgPreprocessor: out[b,t,c,i,j] = img[b,t,c, clamp(i+sy-PAD,0,H-1),
//                                              clamp(j+sx-PAD,0,W-1)] / 255 - 0.5
// img (256,4,3,96,96) fp32, shift (256,2) int32 (sx=shift[b][0], sy=shift[b][1]).
//
// R2: smem row staging. Load phase uses fully ALIGNED float4 LDGs of the
// (Y-shifted, clamped) source rows -> 4x fewer L1 wavefronts than the R1
// scalar-gather. Store phase assembles shifted/clamped output float4 from
// 4 LDS.32 reads (smem BW is not binding). Row stride padded to 100 floats
// to avoid cross-row bank conflicts.

#define PAD 4
#define N_IMG 256
#define T_IMG 4
#define C_IMG 3
#define H_IMG 96
#define W_IMG 96
#define W4 (W_IMG / 4)          // 24 float4 per row
#define TC (T_IMG * C_IMG)      // 12
#define TOTAL_ROWS (N_IMG * TC * H_IMG)   // 294912

#define ROWS_PER_BLOCK 32
#define ROW_STRIDE 100          // floats; 400B, 16B-aligned, 100%32==4 -> staggers banks
#define THREADS 256
#define SLOTS (ROWS_PER_BLOCK * W4)       // 768 float4 slots per block

__global__ __launch_bounds__(THREADS) void shift_img_kernel(
    const float* __restrict__ img,
    const int*   __restrict__ shift,
    float*       __restrict__ out)
{
    __shared__ float rows[ROWS_PER_BLOCK * ROW_STRIDE];

    const int tid      = threadIdx.x;
    const int row0     = blockIdx.x * ROWS_PER_BLOCK;
    const float INV255 = 1.0f / 255.0f;

    // ---- Load phase: stage Y-shifted source rows with aligned float4 LDGs ----
    #pragma unroll
    for (int s = tid; s < SLOTS; s += THREADS) {
        int r       = s / W4;            // local row
        int q       = s % W4;            // float4 slot in row
        int grow    = row0 + r;          // global output row
        int i       = grow % H_IMG;
        int img_idx = grow / H_IMG;      // flattened (b,t,c)
        int b       = img_idx / TC;

        int sy   = __ldg(&shift[2 * b + 1]);
        int srcY = min(max(i + sy - PAD, 0), H_IMG - 1);

        const float4* src = reinterpret_cast<const float4*>(
            img + (size_t)img_idx * (H_IMG * W_IMG) + (size_t)srcY * W_IMG);
        float4 v = __ldg(src + q);

        *reinterpret_cast<float4*>(&rows[r * ROW_STRIDE + 4 * q]) = v;
    }

    __syncthreads();

    // ---- Store phase: shifted/clamped reads from smem, fused normalize ----
    #pragma unroll
    for (int s = tid; s < SLOTS; s += THREADS) {
        int r       = s / W4;
        int q       = s % W4;
        int grow    = row0 + r;
        int img_idx = grow / H_IMG;
        int b       = img_idx / TC;

        int sx   = __ldg(&shift[2 * b + 0]);
        int xoff = 4 * q + sx - PAD;

        const float* sr = &rows[r * ROW_STRIDE];
        int x0 = min(max(xoff + 0, 0), W_IMG - 1);
        int x1 = min(max(xoff + 1, 0), W_IMG - 1);
        int x2 = min(max(xoff + 2, 0), W_IMG - 1);
        int x3 = min(max(xoff + 3, 0), W_IMG - 1);

        float4 v;
        v.x = fmaf(sr[x0], INV255, -0.5f);
        v.y = fmaf(sr[x1], INV255, -0.5f);
        v.z = fmaf(sr[x2], INV255, -0.5f);
        v.w = fmaf(sr[x3], INV255, -0.5f);

        reinterpret_cast<float4*>(out)[(size_t)grow * W4 + q] = v;
    }
}

extern "C" void kernel_launch(void* const* d_in, const int* in_sizes, int n_in,
                              void* d_out, int out_size)
{
    const float* img   = (const float*)d_in[0];
    const int*   shift = (const int*)d_in[1];
    float*       out   = (float*)d_out;

    int blocks = TOTAL_ROWS / ROWS_PER_BLOCK;   // 9216
    shift_img_kernel<<<blocks, THREADS>>>(img, shift, out);
}